// round 4
// baseline (speedup 1.0000x reference)
#include <cuda_runtime.h>
#include <math.h>

#define BB    2
#define NN    2048
#define EE    32768
#define FIN   256
#define NH    8
#define HID   8
#define F1    64
#define FOUT  64

#define NB    148
#define NT    1024

// ---------------- scratch ------------------------------------------------------
__device__ float g_h1[BB * NN * F1];
__device__ float g_s1[BB * NN * NH];
__device__ float g_s2[BB * NN * NH];
__device__ float g_h2[BB * NN * FOUT];
__device__ float g_t1[BB * NN];
__device__ float g_t2[BB * NN];
__device__ int   g_cnt[NN];
__device__ int   g_offs[NN];
__device__ int   g_tgt[EE];
__device__ float g_mean1[BB * F1];      // invariant: zero at launch entry
__device__ float g_mean2[BB * FOUT];    // invariant: zero at launch entry
__device__ unsigned long long g_bar[4]; // monotonic generation counters

__device__ __forceinline__ void gridbar(int slot) {
    __threadfence();
    __syncthreads();
    if (threadIdx.x == 0) {
        unsigned long long old = atomicAdd(&g_bar[slot], 1ULL);
        unsigned long long target = (old / NB + 1ULL) * (unsigned long long)NB;
        volatile unsigned long long* p = (volatile unsigned long long*)&g_bar[slot];
        while (*p < target) { }
    }
    __syncthreads();
}

__device__ __forceinline__ float lrelu(float e) { return fmaxf(e, 0.2f * e); }

__global__ void __launch_bounds__(NT, 1) mega(
    const float* __restrict__ x,
    const int*   __restrict__ edges,
    const float* __restrict__ Wh,
    const float* __restrict__ ah,
    const float* __restrict__ bh,
    const float* __restrict__ Wo,
    const float* __restrict__ ao,
    const float* __restrict__ bo,
    float* __restrict__ out)
{
    const int tid = threadIdx.x;
    const int bid = blockIdx.x;
    __shared__ float sm[12288];   // 48KB, phase-multiplexed

    // ========== P1: CSR build (bid 128) || GEMM1 (bid 0..127) ==========
    if (bid == 128) {
        int* scnt = (int*)sm;            // 2048
        int* pps  = (int*)sm + 2048;     // 1024
        for (int i = tid; i < NN; i += NT) scnt[i] = 0;
        __syncthreads();
        for (int i = tid; i < EE; i += NT) atomicAdd(&scnt[edges[i]], 1);
        __syncthreads();
        int a = scnt[2 * tid], b2 = scnt[2 * tid + 1];
        pps[tid] = a + b2;
        __syncthreads();
        for (int off = 1; off < NT; off <<= 1) {
            int v = pps[tid];
            int ad = (tid >= off) ? pps[tid - off] : 0;
            __syncthreads();
            pps[tid] = v + ad;
            __syncthreads();
        }
        int excl = pps[tid] - (a + b2);
        g_offs[2 * tid]     = excl;
        g_offs[2 * tid + 1] = excl + a;
        scnt[2 * tid]       = excl;      // write cursors
        scnt[2 * tid + 1]   = excl + a;
        __syncthreads();
        for (int i = tid; i < EE; i += NT) {
            int s = edges[i];
            int slot = atomicAdd(&scnt[s], 1);
            g_tgt[slot] = edges[EE + i];
        }
        __syncthreads();
        // dedup + compact (serial per node; deg ~16)
        for (int n = tid; n < NN; n += NT) {
            int st = g_offs[n], en = scnt[n];
            int w = st;
            for (int i = st; i < en; i++) {
                int t = g_tgt[i];
                bool dup = false;
                for (int q = st; q < w; q++)
                    if (g_tgt[q] == t) { dup = true; break; }
                if (!dup) g_tgt[w++] = t;
            }
            g_cnt[n] = w - st;
        }
    } else if (bid < 128) {
        // GEMM1: 32-row tile; smem-resident weights (f-pair interleaved) + x
        const int R = bid * 32;
        const int b = R >> 11;
        const int j = tid & 63, rq = tid >> 6;
        const int h = j >> 3, o = j & 7;
        float* sWp = sm;            // 8192 floats: [f2][2j+p]
        float* sxt = sm + 8192;     // 4096 floats: 32 rows x 128 f
        float a0 = 0.f, b0 = 0.f, a1 = 0.f, b1 = 0.f;
        const float4* x4 = (const float4*)x;
        for (int c = 0; c < 2; c++) {
            __syncthreads();   // prior chunk consumed
            for (int idx = tid; idx < 8192; idx += NT) {
                int f2 = idx >> 7, rem = idx & 127;
                int jj = rem >> 1, p = rem & 1;
                int f = c * 128 + f2 * 2 + p;
                sWp[idx] = __ldg(&Wh[(jj >> 3) * (FIN * HID) + f * HID + (jj & 7)]);
            }
            {
                int r = tid >> 5, f4 = tid & 31;
                ((float4*)sxt)[tid] = x4[(size_t)(R + r) * 64 + c * 32 + f4];
            }
            __syncthreads();
            const float2* xr0 = (const float2*)(sxt + (rq * 2) * 128);
            const float2* xr1 = (const float2*)(sxt + (rq * 2 + 1) * 128);
            const float2* wp  = (const float2*)sWp;
#pragma unroll 16
            for (int f2 = 0; f2 < 64; f2++) {
                float2 w2 = wp[f2 * 64 + j];
                float2 x0 = xr0[f2];
                float2 x1 = xr1[f2];
                a0 = fmaf(x0.x, w2.x, a0); b0 = fmaf(x0.y, w2.y, b0);
                a1 = fmaf(x1.x, w2.x, a1); b1 = fmaf(x1.y, w2.y, b1);
            }
        }
        float acc0 = a0 + b0, acc1 = a1 + b1;
        int r0 = R + rq * 2, r1 = r0 + 1;
        g_h1[(size_t)r0 * F1 + j] = acc0;
        g_h1[(size_t)r1 * F1 + j] = acc1;
        float s1c = __ldg(&ah[h * 16 + o]);
        float s2c = __ldg(&ah[h * 16 + 8 + o]);
        float p10 = acc0 * s1c, p20 = acc0 * s2c;
        float p11 = acc1 * s1c, p21 = acc1 * s2c;
#pragma unroll
        for (int d = 1; d < 8; d <<= 1) {
            p10 += __shfl_xor_sync(0xffffffffu, p10, d);
            p20 += __shfl_xor_sync(0xffffffffu, p20, d);
            p11 += __shfl_xor_sync(0xffffffffu, p11, d);
            p21 += __shfl_xor_sync(0xffffffffu, p21, d);
        }
        if (o == 0) {
            g_s1[r0 * NH + h] = p10; g_s2[r0 * NH + h] = p20;
            g_s1[r1 * NH + h] = p11; g_s2[r1 * NH + h] = p21;
        }
        __syncthreads();                 // done reading sxt
        float* sred = sm + 8192;
        sred[tid] = acc0 + acc1;
        __syncthreads();
        for (int st = 512; st >= 64; st >>= 1) {
            if (tid < st) sred[tid] += sred[tid + st];
            __syncthreads();
        }
        if (tid < 64) atomicAdd(&g_mean1[b * F1 + tid], sred[tid] * (1.0f / NN));
    }
    gridbar(0);

    // ========== P2: att1 + ELU + GEMM2 + scores + mean2 (bid 0..127) ==========
    if (bid < 128) {
        float* sWo = sm;            // 4096
        float* sx1 = sm + 4096;     // 1024 (16 rows x 64)
        float* sp  = sm + 5120;     // 64
        float* sr2 = sm + 5248;     // 1024
        for (int i = tid; i < 1024; i += NT)
            ((float4*)sWo)[i] = ((const float4*)Wo)[i];
        __syncthreads();
        const int j = tid & 63, sub = tid >> 6;
        const int h = j >> 3;
        const float bias = __ldg(&bh[j]);
        const float ao1 = __ldg(&ao[j]), ao2 = __ldg(&ao[FOUT + j]);
        float msum = 0.f;
        const int bB = bid >> 6;   // batch of this block's rows
        for (int g2 = 0; g2 < 2; g2++) {
            int r = bid * 32 + g2 * 16 + sub;
            int b = r >> 11, n = r & (NN - 1);
            int st = g_offs[n], deg = g_cnt[n];
            const int*   tg = g_tgt + st;
            const float* s2p = g_s2 + (size_t)b * NN * NH + h;
            const float* h1p = g_h1 + (size_t)b * NN * F1 + j;
            float outv;
            if (deg == 0) {
                outv = g_mean1[b * F1 + j] + bias;
            } else {
                float s1v = g_s1[(b * NN + n) * NH + h];
                float m = -1e30f;
                int k = 0;
                for (; k + 4 <= deg; k += 4) {
                    int t0 = tg[k], t1 = tg[k+1], t2 = tg[k+2], t3 = tg[k+3];
                    float e0 = lrelu(s1v + s2p[t0 * NH]);
                    float e1 = lrelu(s1v + s2p[t1 * NH]);
                    float e2 = lrelu(s1v + s2p[t2 * NH]);
                    float e3 = lrelu(s1v + s2p[t3 * NH]);
                    m = fmaxf(m, fmaxf(fmaxf(e0, e1), fmaxf(e2, e3)));
                }
                for (; k < deg; k++)
                    m = fmaxf(m, lrelu(s1v + s2p[tg[k] * NH]));
                float den = 0.f, acc = 0.f;
                k = 0;
                for (; k + 4 <= deg; k += 4) {
                    int t0 = tg[k], t1 = tg[k+1], t2 = tg[k+2], t3 = tg[k+3];
                    float e0 = lrelu(s1v + s2p[t0 * NH]);
                    float e1 = lrelu(s1v + s2p[t1 * NH]);
                    float e2 = lrelu(s1v + s2p[t2 * NH]);
                    float e3 = lrelu(s1v + s2p[t3 * NH]);
                    float h0 = h1p[t0 * F1], h1v = h1p[t1 * F1];
                    float h2v = h1p[t2 * F1], h3 = h1p[t3 * F1];
                    float w0 = __expf(e0 - m), w1 = __expf(e1 - m);
                    float w2 = __expf(e2 - m), w3 = __expf(e3 - m);
                    den += (w0 + w1) + (w2 + w3);
                    acc += fmaf(w0, h0, w1 * h1v) + fmaf(w2, h2v, w3 * h3);
                }
                for (; k < deg; k++) {
                    int t = tg[k];
                    float e = lrelu(s1v + s2p[t * NH]);
                    float w = __expf(e - m);
                    den += w;
                    acc = fmaf(w, h1p[t * F1], acc);
                }
                outv = acc / den + bias;
            }
            float x1v = (outv > 0.f) ? outv : (__expf(outv) - 1.0f);
            sx1[sub * 64 + j] = x1v;
            __syncthreads();
            // GEMM2 for this row from smem
            const float* xs = sx1 + sub * 64;
            float hacc = 0.f;
#pragma unroll 16
            for (int f = 0; f < F1; f++) hacc = fmaf(xs[f], sWo[f * FOUT + j], hacc);
            g_h2[(size_t)r * FOUT + j] = hacc;
            msum += hacc;
            float p1 = hacc * ao1, p2 = hacc * ao2;
#pragma unroll
            for (int d = 16; d >= 1; d >>= 1) {
                p1 += __shfl_xor_sync(0xffffffffu, p1, d);
                p2 += __shfl_xor_sync(0xffffffffu, p2, d);
            }
            int warp = tid >> 5;
            if ((tid & 31) == 0) { sp[warp * 2] = p1; sp[warp * 2 + 1] = p2; }
            __syncthreads();
            if (j == 0) {
                g_t1[r] = sp[(sub * 2) * 2]     + sp[(sub * 2 + 1) * 2];
                g_t2[r] = sp[(sub * 2) * 2 + 1] + sp[(sub * 2 + 1) * 2 + 1];
            }
            __syncthreads();
        }
        sr2[tid] = msum;
        __syncthreads();
        for (int st = 512; st >= 64; st >>= 1) {
            if (tid < st) sr2[tid] += sr2[tid + st];
            __syncthreads();
        }
        if (tid < 64) atomicAdd(&g_mean2[bB * FOUT + tid], sr2[tid] * (1.0f / NN));
    }
    gridbar(1);

    // ========== P3: att2 -> out ==========
    {
        const int j = tid & 63, sub = tid >> 6;
        const float bias = __ldg(&bo[j]);
        for (int g = bid; g < (BB * NN) / 16; g += NB) {
            int r = g * 16 + sub;
            int b = r >> 11, n = r & (NN - 1);
            int st = g_offs[n], deg = g_cnt[n];
            const int*   tg = g_tgt + st;
            const float* t2p = g_t2 + (size_t)b * NN;
            const float* h2p = g_h2 + (size_t)b * NN * FOUT + j;
            float outv;
            if (deg == 0) {
                outv = g_mean2[b * FOUT + j] + bias;
            } else {
                float s1v = g_t1[b * NN + n];
                float m = -1e30f;
                int k = 0;
                for (; k + 4 <= deg; k += 4) {
                    int t0 = tg[k], t1 = tg[k+1], t2 = tg[k+2], t3 = tg[k+3];
                    float e0 = lrelu(s1v + t2p[t0]);
                    float e1 = lrelu(s1v + t2p[t1]);
                    float e2 = lrelu(s1v + t2p[t2]);
                    float e3 = lrelu(s1v + t2p[t3]);
                    m = fmaxf(m, fmaxf(fmaxf(e0, e1), fmaxf(e2, e3)));
                }
                for (; k < deg; k++)
                    m = fmaxf(m, lrelu(s1v + t2p[tg[k]]));
                float den = 0.f, acc = 0.f;
                k = 0;
                for (; k + 4 <= deg; k += 4) {
                    int t0 = tg[k], t1 = tg[k+1], t2 = tg[k+2], t3 = tg[k+3];
                    float e0 = lrelu(s1v + t2p[t0]);
                    float e1 = lrelu(s1v + t2p[t1]);
                    float e2 = lrelu(s1v + t2p[t2]);
                    float e3 = lrelu(s1v + t2p[t3]);
                    float h0 = h2p[t0 * FOUT], h1v = h2p[t1 * FOUT];
                    float h2v = h2p[t2 * FOUT], h3 = h2p[t3 * FOUT];
                    float w0 = __expf(e0 - m), w1 = __expf(e1 - m);
                    float w2 = __expf(e2 - m), w3 = __expf(e3 - m);
                    den += (w0 + w1) + (w2 + w3);
                    acc += fmaf(w0, h0, w1 * h1v) + fmaf(w2, h2v, w3 * h3);
                }
                for (; k < deg; k++) {
                    int t = tg[k];
                    float e = lrelu(s1v + t2p[t]);
                    float w = __expf(e - m);
                    den += w;
                    acc = fmaf(w, h2p[t * FOUT], acc);
                }
                outv = acc / den + bias;
            }
            out[(size_t)r * FOUT + j] = outv;
        }
    }
    gridbar(2);

    // ========== P4: log_softmax per (b,o) column (bid 0..127) || cleanup ==========
    if (bid < 128) {
        int b = bid >> 6, o = bid & 63;
        float* sred = sm;
        const float* base = out + (size_t)b * NN * FOUT + o;
        float v0 = base[(size_t)tid * FOUT];
        float v1 = base[(size_t)(tid + NT) * FOUT];
        sred[tid] = fmaxf(v0, v1);
        __syncthreads();
        for (int st = 512; st > 0; st >>= 1) {
            if (tid < st) sred[tid] = fmaxf(sred[tid], sred[tid + st]);
            __syncthreads();
        }
        float mm = sred[0];
        __syncthreads();
        sred[tid] = __expf(v0 - mm) + __expf(v1 - mm);
        __syncthreads();
        for (int st = 512; st > 0; st >>= 1) {
            if (tid < st) sred[tid] += sred[tid + st];
            __syncthreads();
        }
        float lse = mm + __logf(sred[0]);
        float* bw = out + (size_t)b * NN * FOUT + o;
        bw[(size_t)tid * FOUT]        = v0 - lse;
        bw[(size_t)(tid + NT) * FOUT] = v1 - lse;
    } else if (bid == 128) {
        // restore zero-invariant for next launch/replay
        if (tid < BB * F1)                  g_mean1[tid] = 0.f;
        else if (tid < BB * (F1 + FOUT))    g_mean2[tid - BB * F1] = 0.f;
    }
}

// ---------------- launch -------------------------------------------------------
extern "C" void kernel_launch(void* const* d_in, const int* in_sizes, int n_in,
                              void* d_out, int out_size) {
    const float* x     = (const float*)d_in[0];
    const int*   edges = (const int*)  d_in[1];
    const float* Wh    = (const float*)d_in[2];
    const float* ah    = (const float*)d_in[3];
    const float* bh    = (const float*)d_in[4];
    const float* Wo    = (const float*)d_in[5];
    const float* ao    = (const float*)d_in[6];
    const float* bo    = (const float*)d_in[7];
    float* out = (float*)d_out;

    mega<<<NB, NT>>>(x, edges, Wh, ah, bh, Wo, ao, bo, out);
}

// round 5
// speedup vs baseline: 1.6793x; 1.6793x over previous
#include <cuda_runtime.h>
#include <math.h>

// Problem constants (fixed by the dataset)
#define BB    2
#define NN    2048
#define EE    32768
#define FIN   256
#define NH    8
#define HID   8
#define F1    64
#define FOUT  64

#define NB    148     // exactly one block per SM
#define NT    1024
#define NWORDS (NN*NN/32)

// ---------------- scratch (device globals; zero-init at module load) ----------
__device__ float g_h1[BB * NN * F1];
__device__ float g_s1[BB * NN * NH];
__device__ float g_s2[BB * NN * NH];
__device__ float g_x1[BB * NN * F1];
__device__ float g_h2[BB * NN * FOUT];
__device__ float g_t1[BB * NN];
__device__ float g_t2[BB * NN];
__device__ int   g_cnt[NN];
__device__ int   g_offs[NN + 1];
__device__ int   g_tgt[EE];
__device__ unsigned g_bm[NWORDS];       // invariant: all-zero at launch entry
__device__ float g_mean1[BB * F1];      // invariant: zero at launch entry
__device__ float g_mean2[BB * FOUT];    // invariant: zero at launch entry
__device__ unsigned long long g_bar[8]; // monotonic generation counters

__device__ __forceinline__ void gridbar(int slot) {
    __threadfence();
    __syncthreads();
    if (threadIdx.x == 0) {
        unsigned long long old = atomicAdd(&g_bar[slot], 1ULL);
        unsigned long long target = (old / NB + 1ULL) * (unsigned long long)NB;
        volatile unsigned long long* p = (volatile unsigned long long*)&g_bar[slot];
        while (*p < target) { }
    }
    __syncthreads();
}

__device__ __forceinline__ float lrelu(float e) { return fmaxf(e, 0.2f * e); }

__global__ void __launch_bounds__(NT, 1) mega(
    const float* __restrict__ x,
    const int*   __restrict__ edges,
    const float* __restrict__ Wh,
    const float* __restrict__ ah,
    const float* __restrict__ bh,
    const float* __restrict__ Wo,
    const float* __restrict__ ao,
    const float* __restrict__ bo,
    float* __restrict__ out)
{
    const int tid = threadIdx.x;
    const int bid = blockIdx.x;

    __shared__ float sx[8192];      // 32KB: x tile / CSR counters
    __shared__ float sred[1024];    // 4KB : reductions / scan temp

    // ================= Phase 1: CSR build (block NB-1) || GEMM1 (blocks 0..127)
    if (bid == NB - 1) {
        int* scnt = (int*)sx;           // 2048 counters
        int* pps  = (int*)sred;         // 1024 scan temp
        for (int i = tid; i < NN; i += NT) scnt[i] = 0;
        __syncthreads();
        for (int i = tid; i < EE; i += NT) atomicAdd(&scnt[edges[i]], 1);
        __syncthreads();
        int a = scnt[2 * tid], b2 = scnt[2 * tid + 1];
        pps[tid] = a + b2;
        __syncthreads();
        for (int off = 1; off < NT; off <<= 1) {
            int v = pps[tid];
            int ad = (tid >= off) ? pps[tid - off] : 0;
            __syncthreads();
            pps[tid] = v + ad;
            __syncthreads();
        }
        int excl = pps[tid] - (a + b2);
        g_offs[2 * tid]     = excl;
        g_offs[2 * tid + 1] = excl + a;
        if (tid == NT - 1) g_offs[NN] = pps[tid];
        scnt[2 * tid]     = excl;          // write cursors
        scnt[2 * tid + 1] = excl + a;
        __syncthreads();
        for (int i = tid; i < EE; i += NT) {
            int s = edges[i], t = edges[EE + i];
            unsigned bit = (unsigned)s * NN + (unsigned)t;
            unsigned msk = 1u << (bit & 31u);
            unsigned old = atomicOr(&g_bm[bit >> 5], msk);
            if (!(old & msk)) {
                int slot = atomicAdd(&scnt[s], 1);
                g_tgt[slot] = t;
            }
        }
        __syncthreads();
        for (int n = tid; n < NN; n += NT) g_cnt[n] = scnt[n] - g_offs[n];
    } else if (bid < 128) {
        // GEMM1: 32-row tile, 2 rows/thread, h1 = x @ Wh + scores + mean atomics
        const int R = bid * 32;
        const int b = R >> 11;
        const float4* x4 = (const float4*)x + (size_t)R * (FIN / 4);
        float4* sx4 = (float4*)sx;
        for (int i = tid; i < 32 * (FIN / 4); i += NT) sx4[i] = x4[i];
        __syncthreads();
        const int j = tid & 63, rq = tid >> 6;        // 16 quads x 2 rows
        const int h = j >> 3, o = j & 7;
        const float* w   = Wh + h * (FIN * HID) + o;
        const float* xr0 = sx + (rq * 2) * FIN;
        const float* xr1 = xr0 + FIN;
        float a0 = 0.f, a1 = 0.f, c0 = 0.f, c1 = 0.f;
#pragma unroll 8
        for (int f = 0; f < FIN; f += 2) {
            float w0 = __ldg(&w[f * HID]);
            float w1 = __ldg(&w[(f + 1) * HID]);
            a0 = fmaf(xr0[f], w0, a0);     c0 = fmaf(xr1[f], w0, c0);
            a1 = fmaf(xr0[f + 1], w1, a1); c1 = fmaf(xr1[f + 1], w1, c1);
        }
        float acc0 = a0 + a1, acc1 = c0 + c1;
        int r0 = R + rq * 2, r1 = r0 + 1;
        g_h1[(size_t)r0 * F1 + j] = acc0;
        g_h1[(size_t)r1 * F1 + j] = acc1;
        float s1c = __ldg(&ah[h * 16 + o]);
        float s2c = __ldg(&ah[h * 16 + 8 + o]);
        float p10 = acc0 * s1c, p20 = acc0 * s2c;
        float p11 = acc1 * s1c, p21 = acc1 * s2c;
#pragma unroll
        for (int d = 1; d < 8; d <<= 1) {
            p10 += __shfl_xor_sync(0xffffffffu, p10, d);
            p20 += __shfl_xor_sync(0xffffffffu, p20, d);
            p11 += __shfl_xor_sync(0xffffffffu, p11, d);
            p21 += __shfl_xor_sync(0xffffffffu, p21, d);
        }
        if (o == 0) {
            g_s1[r0 * NH + h] = p10; g_s2[r0 * NH + h] = p20;
            g_s1[r1 * NH + h] = p11; g_s2[r1 * NH + h] = p21;
        }
        sred[tid] = acc0 + acc1;
        __syncthreads();
        for (int st = 512; st >= 64; st >>= 1) {
            if (tid < st) sred[tid] += sred[tid + st];
            __syncthreads();
        }
        if (tid < 64) atomicAdd(&g_mean1[b * F1 + tid], sred[tid] * (1.0f / NN));
    }
    gridbar(0);

    // ================= Phase 2: att1 + ELU (two-pass, 4-wide)
    {
        const int j = tid & 63, sub = tid >> 6;   // 16 rows per group
        const int h = j >> 3;
        const float bias = __ldg(&bh[j]);
        for (int g = bid; g < (BB * NN) / 16; g += NB) {
            int r = g * 16 + sub;
            int b = r >> 11, n = r & (NN - 1);
            int st = g_offs[n], deg = g_cnt[n];
            const int*   tg  = g_tgt + st;
            const float* s2p = g_s2 + (size_t)b * NN * NH + h;
            const float* h1p = g_h1 + (size_t)b * NN * F1 + j;
            float outv;
            if (deg == 0) {
                outv = g_mean1[b * F1 + j] + bias;
            } else {
                float s1v = g_s1[(b * NN + n) * NH + h];
                float m = -1e30f;
                int k = 0;
                for (; k + 4 <= deg; k += 4) {
                    int t0 = tg[k], t1 = tg[k+1], t2 = tg[k+2], t3 = tg[k+3];
                    float e0 = lrelu(s1v + s2p[t0 * NH]);
                    float e1 = lrelu(s1v + s2p[t1 * NH]);
                    float e2 = lrelu(s1v + s2p[t2 * NH]);
                    float e3 = lrelu(s1v + s2p[t3 * NH]);
                    m = fmaxf(m, fmaxf(fmaxf(e0, e1), fmaxf(e2, e3)));
                }
                for (; k < deg; k++)
                    m = fmaxf(m, lrelu(s1v + s2p[tg[k] * NH]));
                float den = 0.f, acc = 0.f;
                k = 0;
                for (; k + 4 <= deg; k += 4) {
                    int t0 = tg[k], t1 = tg[k+1], t2 = tg[k+2], t3 = tg[k+3];
                    float e0 = lrelu(s1v + s2p[t0 * NH]);
                    float e1 = lrelu(s1v + s2p[t1 * NH]);
                    float e2 = lrelu(s1v + s2p[t2 * NH]);
                    float e3 = lrelu(s1v + s2p[t3 * NH]);
                    float h0 = h1p[t0 * F1], h1v = h1p[t1 * F1];
                    float h2v = h1p[t2 * F1], h3 = h1p[t3 * F1];
                    float w0 = __expf(e0 - m), w1 = __expf(e1 - m);
                    float w2 = __expf(e2 - m), w3 = __expf(e3 - m);
                    den += (w0 + w1) + (w2 + w3);
                    acc += fmaf(w0, h0, w1 * h1v) + fmaf(w2, h2v, w3 * h3);
                }
                for (; k < deg; k++) {
                    int t = tg[k];
                    float e = lrelu(s1v + s2p[t * NH]);
                    float wgt = __expf(e - m);
                    den += wgt;
                    acc = fmaf(wgt, h1p[t * F1], acc);
                }
                outv = acc / den + bias;
            }
            g_x1[(size_t)r * F1 + j] = (outv > 0.f) ? outv : (__expf(outv) - 1.0f);
        }
    }
    gridbar(1);

    // ================= Phase 3: GEMM2 + scores + mean2 (blocks 0..127)
    if (bid < 128) {
        const int R = bid * 32;
        const int b = R >> 11;
        for (int i = tid; i < 32 * F1; i += NT) sx[i] = g_x1[(size_t)R * F1 + i];
        __syncthreads();
        const int j = tid & 63, rq = tid >> 6;
        const float* xr0 = sx + (rq * 2) * F1;
        const float* xr1 = xr0 + F1;
        float a0 = 0.f, c0 = 0.f;
#pragma unroll 16
        for (int f = 0; f < F1; f++) {
            float wv = __ldg(&Wo[f * FOUT + j]);
            a0 = fmaf(xr0[f], wv, a0);
            c0 = fmaf(xr1[f], wv, c0);
        }
        int r0 = R + rq * 2, r1 = r0 + 1;
        g_h2[(size_t)r0 * FOUT + j] = a0;
        g_h2[(size_t)r1 * FOUT + j] = c0;
        float w1c = __ldg(&ao[j]), w2c = __ldg(&ao[FOUT + j]);
        float p10 = a0 * w1c, p20 = a0 * w2c;
        float p11 = c0 * w1c, p21 = c0 * w2c;
#pragma unroll
        for (int d = 16; d >= 1; d >>= 1) {
            p10 += __shfl_xor_sync(0xffffffffu, p10, d);
            p20 += __shfl_xor_sync(0xffffffffu, p20, d);
            p11 += __shfl_xor_sync(0xffffffffu, p11, d);
            p21 += __shfl_xor_sync(0xffffffffu, p21, d);
        }
        int warp = tid >> 5;
        if ((tid & 31) == 0) {
            sred[warp * 4 + 0] = p10; sred[warp * 4 + 1] = p20;
            sred[warp * 4 + 2] = p11; sred[warp * 4 + 3] = p21;
        }
        __syncthreads();
        if (tid < 64) {
            int rq2 = tid >> 2, which = tid & 3;
            float v = sred[(2 * rq2) * 4 + which] + sred[(2 * rq2 + 1) * 4 + which];
            int rr = R + rq2 * 2;
            if      (which == 0) g_t1[rr] = v;
            else if (which == 1) g_t2[rr] = v;
            else if (which == 2) g_t1[rr + 1] = v;
            else                 g_t2[rr + 1] = v;
        }
        __syncthreads();
        sred[tid] = a0 + c0;
        __syncthreads();
        for (int st = 512; st >= 64; st >>= 1) {
            if (tid < st) sred[tid] += sred[tid + st];
            __syncthreads();
        }
        if (tid < 64) atomicAdd(&g_mean2[b * FOUT + tid], sred[tid] * (1.0f / NN));
    }
    gridbar(2);

    // ================= Phase 4: att2 -> out (two-pass, 4-wide)
    {
        const int j = tid & 63, sub = tid >> 6;
        const float bias = __ldg(&bo[j]);
        for (int g = bid; g < (BB * NN) / 16; g += NB) {
            int r = g * 16 + sub;
            int b = r >> 11, n = r & (NN - 1);
            int st = g_offs[n], deg = g_cnt[n];
            const int*   tg  = g_tgt + st;
            const float* t2p = g_t2 + (size_t)b * NN;
            const float* h2p = g_h2 + (size_t)b * NN * FOUT + j;
            float outv;
            if (deg == 0) {
                outv = g_mean2[b * FOUT + j] + bias;
            } else {
                float s1v = g_t1[b * NN + n];
                float m = -1e30f;
                int k = 0;
                for (; k + 4 <= deg; k += 4) {
                    int t0 = tg[k], t1 = tg[k+1], t2 = tg[k+2], t3 = tg[k+3];
                    float e0 = lrelu(s1v + t2p[t0]);
                    float e1 = lrelu(s1v + t2p[t1]);
                    float e2 = lrelu(s1v + t2p[t2]);
                    float e3 = lrelu(s1v + t2p[t3]);
                    m = fmaxf(m, fmaxf(fmaxf(e0, e1), fmaxf(e2, e3)));
                }
                for (; k < deg; k++)
                    m = fmaxf(m, lrelu(s1v + t2p[tg[k]]));
                float den = 0.f, acc = 0.f;
                k = 0;
                for (; k + 4 <= deg; k += 4) {
                    int t0 = tg[k], t1 = tg[k+1], t2 = tg[k+2], t3 = tg[k+3];
                    float e0 = lrelu(s1v + t2p[t0]);
                    float e1 = lrelu(s1v + t2p[t1]);
                    float e2 = lrelu(s1v + t2p[t2]);
                    float e3 = lrelu(s1v + t2p[t3]);
                    float h0 = h2p[t0 * FOUT], h1v = h2p[t1 * FOUT];
                    float h2v = h2p[t2 * FOUT], h3 = h2p[t3 * FOUT];
                    float w0 = __expf(e0 - m), w1 = __expf(e1 - m);
                    float w2 = __expf(e2 - m), w3 = __expf(e3 - m);
                    den += (w0 + w1) + (w2 + w3);
                    acc += fmaf(w0, h0, w1 * h1v) + fmaf(w2, h2v, w3 * h3);
                }
                for (; k < deg; k++) {
                    int t = tg[k];
                    float e = lrelu(s1v + t2p[t]);
                    float wgt = __expf(e - m);
                    den += wgt;
                    acc = fmaf(wgt, h2p[t * FOUT], acc);
                }
                outv = acc / den + bias;
            }
            out[(size_t)r * FOUT + j] = outv;
        }
    }
    gridbar(3);

    // ================= Phase 5: log_softmax (blocks 0..127) || state cleanup
    if (bid < 128) {
        int b = bid >> 6, o = bid & 63;
        const float* base = out + (size_t)b * NN * FOUT + o;
        float v0 = base[(size_t)tid * FOUT];
        float v1 = base[(size_t)(tid + NT) * FOUT];
        sred[tid] = fmaxf(v0, v1);
        __syncthreads();
        for (int st = 512; st > 0; st >>= 1) {
            if (tid < st) sred[tid] = fmaxf(sred[tid], sred[tid + st]);
            __syncthreads();
        }
        float mm = sred[0];
        __syncthreads();
        sred[tid] = __expf(v0 - mm) + __expf(v1 - mm);
        __syncthreads();
        for (int st = 512; st > 0; st >>= 1) {
            if (tid < st) sred[tid] += sred[tid + st];
            __syncthreads();
        }
        float lse = mm + __logf(sred[0]);
        float* basew = out + (size_t)b * NN * FOUT + o;
        basew[(size_t)tid * FOUT]        = v0 - lse;
        basew[(size_t)(tid + NT) * FOUT] = v1 - lse;
    } else {
        // restore launch-entry invariants: bitmap bits + means back to zero
        int cb = bid - 128;   // 0..19
        for (int i = cb * NT + tid; i < EE; i += 20 * NT) {
            int s = edges[i], t = edges[EE + i];
            unsigned bit = (unsigned)s * NN + (unsigned)t;
            atomicAnd(&g_bm[bit >> 5], ~(1u << (bit & 31u)));
        }
        if (cb == 0) {
            if (tid < BB * F1)                       g_mean1[tid] = 0.f;
            else if (tid < BB * F1 + BB * FOUT)      g_mean2[tid - BB * F1] = 0.f;
        }
    }
}

// ---------------- launch -------------------------------------------------------
extern "C" void kernel_launch(void* const* d_in, const int* in_sizes, int n_in,
                              void* d_out, int out_size) {
    const float* x     = (const float*)d_in[0];
    const int*   edges = (const int*)  d_in[1];
    const float* Wh    = (const float*)d_in[2];
    const float* ah    = (const float*)d_in[3];
    const float* bh    = (const float*)d_in[4];
    const float* Wo    = (const float*)d_in[5];
    const float* ao    = (const float*)d_in[6];
    const float* bo    = (const float*)d_in[7];
    float* out = (float*)d_out;

    mega<<<NB, NT>>>(x, edges, Wh, ah, bh, Wo, ao, bo, out);
}

// round 7
// speedup vs baseline: 1.8686x; 1.1128x over previous
#include <cuda_runtime.h>
#include <math.h>

#define BB    2
#define NN    2048
#define EE    32768
#define FIN   256
#define NH    8
#define HID   8
#define F1    64
#define FOUT  64

#define NB    148
#define NT    1024
#define NWORDS (NN*NN/32)

// ---------------- scratch ------------------------------------------------------
__device__ float g_h1[BB * NN * F1];
__device__ float g_s1[BB * NN * NH];
__device__ float g_s2[BB * NN * NH];
__device__ float g_h2[BB * NN * FOUT];
__device__ float g_t1[BB * NN];
__device__ float g_t2[BB * NN];
__device__ int   g_cnt[NN];
__device__ int   g_offs[NN + 1];
__device__ int   g_tgt[EE];
__device__ unsigned g_bm[NWORDS];       // invariant: all-zero at launch entry
__device__ float g_mean1[BB * F1];      // invariant: zero at launch entry
__device__ float g_mean2[BB * FOUT];    // invariant: zero at launch entry
__device__ unsigned long long g_bar[8];

__device__ __forceinline__ void gridbar(int slot) {
    __threadfence();
    __syncthreads();
    if (threadIdx.x == 0) {
        unsigned long long old = atomicAdd(&g_bar[slot], 1ULL);
        unsigned long long target = (old / NB + 1ULL) * (unsigned long long)NB;
        volatile unsigned long long* p = (volatile unsigned long long*)&g_bar[slot];
        while (*p < target) { }
    }
    __syncthreads();
}

__device__ __forceinline__ float lrelu(float e) { return fmaxf(e, 0.2f * e); }

__global__ void __launch_bounds__(NT, 1) mega(
    const float* __restrict__ x,
    const int*   __restrict__ edges,
    const float* __restrict__ Wh,
    const float* __restrict__ ah,
    const float* __restrict__ bh,
    const float* __restrict__ Wo,
    const float* __restrict__ ao,
    const float* __restrict__ bo,
    float* __restrict__ out)
{
    const int tid = threadIdx.x;
    const int bid = blockIdx.x;

    __shared__ float sx[8192];      // 32KB multiplexed
    __shared__ float sred[1024];

    // ===== P1: CSR build (block 147) || GEMM1 (blocks 0..127) =====
    if (bid == NB - 1) {
        int* scnt = (int*)sx;
        int* pps  = (int*)sred;
        for (int i = tid; i < NN; i += NT) scnt[i] = 0;
        __syncthreads();
        for (int i = tid; i < EE; i += NT) atomicAdd(&scnt[edges[i]], 1);
        __syncthreads();
        int a = scnt[2 * tid], b2 = scnt[2 * tid + 1];
        pps[tid] = a + b2;
        __syncthreads();
        for (int off = 1; off < NT; off <<= 1) {
            int v = pps[tid];
            int ad = (tid >= off) ? pps[tid - off] : 0;
            __syncthreads();
            pps[tid] = v + ad;
            __syncthreads();
        }
        int excl = pps[tid] - (a + b2);
        g_offs[2 * tid]     = excl;
        g_offs[2 * tid + 1] = excl + a;
        if (tid == NT - 1) g_offs[NN] = pps[tid];
        scnt[2 * tid]     = excl;
        scnt[2 * tid + 1] = excl + a;
        __syncthreads();
        for (int i = tid; i < EE; i += NT) {
            int s = edges[i], t = edges[EE + i];
            unsigned bit = (unsigned)s * NN + (unsigned)t;
            unsigned msk = 1u << (bit & 31u);
            unsigned old = atomicOr(&g_bm[bit >> 5], msk);
            if (!(old & msk)) {
                int slot = atomicAdd(&scnt[s], 1);
                g_tgt[slot] = t;
            }
        }
        __syncthreads();
        for (int n = tid; n < NN; n += NT) g_cnt[n] = scnt[n] - g_offs[n];
    } else if (bid < 128) {
        const int R = bid * 32;
        const int b = R >> 11;
        const float4* x4 = (const float4*)x + (size_t)R * (FIN / 4);
        float4* sx4 = (float4*)sx;
        for (int i = tid; i < 32 * (FIN / 4); i += NT) sx4[i] = x4[i];
        __syncthreads();
        const int j = tid & 63, rq = tid >> 6;
        const int h = j >> 3, o = j & 7;
        const float* w   = Wh + h * (FIN * HID) + o;
        const float* xr0 = sx + (rq * 2) * FIN;
        const float* xr1 = xr0 + FIN;
        float a0 = 0.f, a1 = 0.f, c0 = 0.f, c1 = 0.f;
#pragma unroll 8
        for (int f = 0; f < FIN; f += 2) {
            float w0 = __ldg(&w[f * HID]);
            float w1 = __ldg(&w[(f + 1) * HID]);
            a0 = fmaf(xr0[f], w0, a0);     c0 = fmaf(xr1[f], w0, c0);
            a1 = fmaf(xr0[f + 1], w1, a1); c1 = fmaf(xr1[f + 1], w1, c1);
        }
        float acc0 = a0 + a1, acc1 = c0 + c1;
        int r0 = R + rq * 2, r1 = r0 + 1;
        g_h1[(size_t)r0 * F1 + j] = acc0;
        g_h1[(size_t)r1 * F1 + j] = acc1;
        float s1c = __ldg(&ah[h * 16 + o]);
        float s2c = __ldg(&ah[h * 16 + 8 + o]);
        float p10 = acc0 * s1c, p20 = acc0 * s2c;
        float p11 = acc1 * s1c, p21 = acc1 * s2c;
#pragma unroll
        for (int d = 1; d < 8; d <<= 1) {
            p10 += __shfl_xor_sync(0xffffffffu, p10, d);
            p20 += __shfl_xor_sync(0xffffffffu, p20, d);
            p11 += __shfl_xor_sync(0xffffffffu, p11, d);
            p21 += __shfl_xor_sync(0xffffffffu, p21, d);
        }
        if (o == 0) {
            g_s1[r0 * NH + h] = p10; g_s2[r0 * NH + h] = p20;
            g_s1[r1 * NH + h] = p11; g_s2[r1 * NH + h] = p21;
        }
        sred[tid] = acc0 + acc1;
        __syncthreads();
        for (int st = 512; st >= 64; st >>= 1) {
            if (tid < st) sred[tid] += sred[tid + st];
            __syncthreads();
        }
        if (tid < 64) atomicAdd(&g_mean1[b * F1 + tid], sred[tid] * (1.0f / NN));
    }
    gridbar(0);

    // ===== P2: att1 + ELU + GEMM2 + scores + mean2 (blocks 0..127, warp/row) =====
    if (bid < 128) {
        // stage Wo into smem (conflict-free by output column)
        for (int i = tid; i < 1024; i += NT)
            ((float4*)sx)[i] = ((const float4*)Wo)[i];
        __syncthreads();
        float* sWo = sx;                 // 4096 floats
        float* sm2 = sx + 4096;          // 2048 floats (32 warps x 64)

        const int w = tid >> 5, lane = tid & 31;
        const int r = bid * 32 + w;      // 0..4095, block-contiguous, batch-uniform
        const int b = r >> 11, n = r & (NN - 1);
        const int j0 = lane, j1 = lane + 32;
        const int h0 = lane >> 3, h1 = h0 + 4;
        const int st = g_offs[n], deg = g_cnt[n];
        const int*   tg  = g_tgt + st;
        const float* s2p = g_s2 + (size_t)b * NN * NH;
        const float* h1p = g_h1 + (size_t)b * NN * F1;
        float o0, o1;
        if (deg == 0) {
            o0 = g_mean1[b * F1 + j0] + __ldg(&bh[j0]);
            o1 = g_mean1[b * F1 + j1] + __ldg(&bh[j1]);
        } else {
            float s1v0 = g_s1[(b * NN + n) * NH + h0];
            float s1v1 = g_s1[(b * NN + n) * NH + h1];
            float m0 = -1e30f, m1 = -1e30f;
            int k = 0;
            for (; k + 2 <= deg; k += 2) {
                int ta = tg[k], tb = tg[k + 1];
                float ea0 = lrelu(s1v0 + s2p[ta * NH + h0]);
                float ea1 = lrelu(s1v1 + s2p[ta * NH + h1]);
                float eb0 = lrelu(s1v0 + s2p[tb * NH + h0]);
                float eb1 = lrelu(s1v1 + s2p[tb * NH + h1]);
                m0 = fmaxf(m0, fmaxf(ea0, eb0));
                m1 = fmaxf(m1, fmaxf(ea1, eb1));
            }
            if (k < deg) {
                int ta = tg[k];
                m0 = fmaxf(m0, lrelu(s1v0 + s2p[ta * NH + h0]));
                m1 = fmaxf(m1, lrelu(s1v1 + s2p[ta * NH + h1]));
            }
            float den0 = 0.f, den1 = 0.f, acc0 = 0.f, acc1 = 0.f;
            k = 0;
            for (; k + 2 <= deg; k += 2) {
                int ta = tg[k], tb = tg[k + 1];
                float ea0 = lrelu(s1v0 + s2p[ta * NH + h0]);
                float ea1 = lrelu(s1v1 + s2p[ta * NH + h1]);
                float eb0 = lrelu(s1v0 + s2p[tb * NH + h0]);
                float eb1 = lrelu(s1v1 + s2p[tb * NH + h1]);
                float ha0 = h1p[ta * F1 + j0], ha1 = h1p[ta * F1 + j1];
                float hb0 = h1p[tb * F1 + j0], hb1 = h1p[tb * F1 + j1];
                float wa0 = __expf(ea0 - m0), wa1 = __expf(ea1 - m1);
                float wb0 = __expf(eb0 - m0), wb1 = __expf(eb1 - m1);
                den0 += wa0 + wb0; den1 += wa1 + wb1;
                acc0 = fmaf(wa0, ha0, fmaf(wb0, hb0, acc0));
                acc1 = fmaf(wa1, ha1, fmaf(wb1, hb1, acc1));
            }
            if (k < deg) {
                int ta = tg[k];
                float ea0 = lrelu(s1v0 + s2p[ta * NH + h0]);
                float ea1 = lrelu(s1v1 + s2p[ta * NH + h1]);
                float wa0 = __expf(ea0 - m0), wa1 = __expf(ea1 - m1);
                den0 += wa0; den1 += wa1;
                acc0 = fmaf(wa0, h1p[ta * F1 + j0], acc0);
                acc1 = fmaf(wa1, h1p[ta * F1 + j1], acc1);
            }
            o0 = acc0 / den0 + __ldg(&bh[j0]);
            o1 = acc1 / den1 + __ldg(&bh[j1]);
        }
        float x1a = (o0 > 0.f) ? o0 : (__expf(o0) - 1.0f);
        float x1b = (o1 > 0.f) ? o1 : (__expf(o1) - 1.0f);

        // GEMM2 via warp shuffles (sync-free within warp)
        float g0 = 0.f, g1 = 0.f;
#pragma unroll
        for (int f = 0; f < 32; f++) {
            float xf = __shfl_sync(0xffffffffu, x1a, f);
            g0 = fmaf(xf, sWo[f * FOUT + j0], g0);
            g1 = fmaf(xf, sWo[f * FOUT + j1], g1);
        }
#pragma unroll
        for (int f = 0; f < 32; f++) {
            float xf = __shfl_sync(0xffffffffu, x1b, f);
            g0 = fmaf(xf, sWo[(f + 32) * FOUT + j0], g0);
            g1 = fmaf(xf, sWo[(f + 32) * FOUT + j1], g1);
        }
        g_h2[(size_t)r * FOUT + j0] = g0;
        g_h2[(size_t)r * FOUT + j1] = g1;
        float p1 = fmaf(g0, __ldg(&ao[j0]), g1 * __ldg(&ao[j1]));
        float p2 = fmaf(g0, __ldg(&ao[FOUT + j0]), g1 * __ldg(&ao[FOUT + j1]));
#pragma unroll
        for (int d = 16; d >= 1; d >>= 1) {
            p1 += __shfl_xor_sync(0xffffffffu, p1, d);
            p2 += __shfl_xor_sync(0xffffffffu, p2, d);
        }
        if (lane == 0) { g_t1[r] = p1; g_t2[r] = p2; }

        // mean2 partials (batch uniform per block)
        sm2[w * 64 + j0] = g0;
        sm2[w * 64 + j1] = g1;
        __syncthreads();
        for (int s = 16; s > 0; s >>= 1) {
            if (w < s) {
                sm2[w * 64 + j0] += sm2[(w + s) * 64 + j0];
                sm2[w * 64 + j1] += sm2[(w + s) * 64 + j1];
            }
            __syncthreads();
        }
        if (tid < 64) atomicAdd(&g_mean2[(bid >> 6) * FOUT + tid], sm2[tid] * (1.0f / NN));
    }
    gridbar(1);

    // ===== P3: att2 -> out (warp-per-row, balanced r = w*148 + bid) =====
    {
        const int w = tid >> 5, lane = tid & 31;
        const int r = w * NB + bid;
        if (r < BB * NN) {
            const int b = r >> 11, n = r & (NN - 1);
            const int st = g_offs[n], deg = g_cnt[n];
            const int*   tg  = g_tgt + st;
            const float* t2p = g_t2 + (size_t)b * NN;
            const float* h2p = g_h2 + (size_t)b * NN * FOUT;
            float o0, o1;
            if (deg == 0) {
                o0 = g_mean2[b * FOUT + lane]      + __ldg(&bo[lane]);
                o1 = g_mean2[b * FOUT + lane + 32] + __ldg(&bo[lane + 32]);
            } else {
                float s1v = g_t1[b * NN + n];
                float m = -1e30f;
                int k = 0;
                for (; k + 4 <= deg; k += 4) {
                    float e0 = lrelu(s1v + t2p[tg[k]]);
                    float e1 = lrelu(s1v + t2p[tg[k + 1]]);
                    float e2 = lrelu(s1v + t2p[tg[k + 2]]);
                    float e3 = lrelu(s1v + t2p[tg[k + 3]]);
                    m = fmaxf(m, fmaxf(fmaxf(e0, e1), fmaxf(e2, e3)));
                }
                for (; k < deg; k++)
                    m = fmaxf(m, lrelu(s1v + t2p[tg[k]]));
                float den = 0.f, a0 = 0.f, a1 = 0.f;
                k = 0;
                for (; k + 2 <= deg; k += 2) {
                    int ta = tg[k], tb = tg[k + 1];
                    float ea = lrelu(s1v + t2p[ta]);
                    float eb = lrelu(s1v + t2p[tb]);
                    float wa = __expf(ea - m), wb = __expf(eb - m);
                    float ha0 = h2p[ta * FOUT + lane], ha1 = h2p[ta * FOUT + lane + 32];
                    float hb0 = h2p[tb * FOUT + lane], hb1 = h2p[tb * FOUT + lane + 32];
                    den += wa + wb;
                    a0 = fmaf(wa, ha0, fmaf(wb, hb0, a0));
                    a1 = fmaf(wa, ha1, fmaf(wb, hb1, a1));
                }
                if (k < deg) {
                    int ta = tg[k];
                    float ea = lrelu(s1v + t2p[ta]);
                    float wa = __expf(ea - m);
                    den += wa;
                    a0 = fmaf(wa, h2p[ta * FOUT + lane], a0);
                    a1 = fmaf(wa, h2p[ta * FOUT + lane + 32], a1);
                }
                o0 = a0 / den + __ldg(&bo[lane]);
                o1 = a1 / den + __ldg(&bo[lane + 32]);
            }
            out[(size_t)r * FOUT + lane]      = o0;
            out[(size_t)r * FOUT + lane + 32] = o1;
        }
    }
    gridbar(2);

    // ===== P4: log_softmax per (b,o) column (blocks 0..127) || cleanup =====
    if (bid < 128) {
        int b = bid >> 6, o = bid & 63;
        const float* base = out + (size_t)b * NN * FOUT + o;
        float v0 = base[(size_t)tid * FOUT];
        float v1 = base[(size_t)(tid + NT) * FOUT];
        sred[tid] = fmaxf(v0, v1);
        __syncthreads();
        for (int st = 512; st > 0; st >>= 1) {
            if (tid < st) sred[tid] = fmaxf(sred[tid], sred[tid + st]);
            __syncthreads();
        }
        float mm = sred[0];
        __syncthreads();
        sred[tid] = __expf(v0 - mm) + __expf(v1 - mm);
        __syncthreads();
        for (int st = 512; st > 0; st >>= 1) {
            if (tid < st) sred[tid] += sred[tid + st];
            __syncthreads();
        }
        float lse = mm + __logf(sred[0]);
        float* basew = out + (size_t)b * NN * FOUT + o;
        basew[(size_t)tid * FOUT]        = v0 - lse;
        basew[(size_t)(tid + NT) * FOUT] = v1 - lse;
    } else {
        int cb = bid - 128;   // 0..19
        for (int i = cb * NT + tid; i < EE; i += 20 * NT) {
            int s = edges[i], t = edges[EE + i];
            unsigned bit = (unsigned)s * NN + (unsigned)t;
            atomicAnd(&g_bm[bit >> 5], ~(1u << (bit & 31u)));
        }
        if (cb == 0) {
            if (tid < BB * F1)                  g_mean1[tid] = 0.f;
            else if (tid < BB * (F1 + FOUT))    g_mean2[tid - BB * F1] = 0.f;
        }
    }
}

// ---------------- launch -------------------------------------------------------
extern "C" void kernel_launch(void* const* d_in, const int* in_sizes, int n_in,
                              void* d_out, int out_size) {
    const float* x     = (const float*)d_in[0];
    const int*   edges = (const int*)  d_in[1];
    const float* Wh    = (const float*)d_in[2];
    const float* ah    = (const float*)d_in[3];
    const float* bh    = (const float*)d_in[4];
    const float* Wo    = (const float*)d_in[5];
    const float* ao    = (const float*)d_in[6];
    const float* bo    = (const float*)d_in[7];
    float* out = (float*)d_out;

    mega<<<NB, NT>>>(x, edges, Wh, ah, bh, Wo, ao, bo, out);
}